// round 1
// baseline (speedup 1.0000x reference)
#include <cuda_runtime.h>
#include <cuda_bf16.h>
#include <math.h>

// Problem constants
#define BATCH 16
#define SEQ   2048
#define HID   256      // H = P = Hin = 256
#define NLAYER 4
#define BNTOT (BATCH*SEQ)          // 32768
#define LS    393728               // packed per-layer weight stride (floats)

// ---------------- scratch (device globals; no allocations allowed) ----------
__device__ float g_V [(size_t)BNTOT*256];        // LN output
__device__ float g_Bu[(size_t)BNTOT*512];        // [Bu_re | Bu_im]
__device__ float g_X [(size_t)2*BNTOT*512];      // rows 0..BN-1: x_right [re|im]; BN..: x_left
__device__ float g_Y [(size_t)2*BNTOT*256];      // y (then gelu(y) in place); also alpha temp
__device__ float g_T [(size_t)2*BNTOT*512];      // [g@W1+b1 | g@W2+b2]
__device__ float g_U [(size_t)2*BNTOT*256];      // rows 0..BN-1: right_u; BN..: left_u
__device__ float g_W [(size_t)NLAYER*LS];        // packed weights

// ---------------- weight packing --------------------------------------------
// per layer: [0,131072)  Bcat (256 x 512):  [B_re | B_im]
//            [131072,262144) Ccat (512 x 256): rows<256 C_re, rows>=256 -C_im
//            [262144,393216) Wcat (256 x 512): [W1 | W2]
//            [393216,393728) biascat (512):    [b1 | b2]
__global__ void pack_kernel(const float* __restrict__ B_re, const float* __restrict__ B_im,
                            const float* __restrict__ C_re, const float* __restrict__ C_im,
                            const float* __restrict__ W1,   const float* __restrict__ W2,
                            const float* __restrict__ b1,   const float* __restrict__ b2,
                            float* __restrict__ W)
{
    int idx = blockIdx.x * blockDim.x + threadIdx.x;
    int total = NLAYER * LS;
    if (idx >= total) return;
    int l = idx / LS;
    int r = idx - l * LS;
    float val;
    if (r < 131072) {                       // Bcat
        int h = r >> 9, j = r & 511;
        val = (j < 256) ? B_re[l*65536 + h*256 + j]
                        : B_im[l*65536 + h*256 + (j-256)];
    } else if (r < 262144) {                // Ccat
        int r2 = r - 131072;
        int k = r2 >> 8, h = r2 & 255;
        val = (k < 256) ? C_re[l*65536 + k*256 + h]
                        : -C_im[l*65536 + (k-256)*256 + h];
    } else if (r < 393216) {                // Wcat
        int r3 = r - 262144;
        int k = r3 >> 9, j = r3 & 511;
        val = (j < 256) ? W1[l*65536 + k*256 + j]
                        : W2[l*65536 + k*256 + (j-256)];
    } else {                                // biascat
        int r4 = r - 393216;
        val = (r4 < 256) ? b1[l*256 + r4] : b2[l*256 + (r4-256)];
    }
    W[idx] = val;
}

// ---------------- SGEMM: C = A(MxK) * B(KxN) [+ bias(N)], row-major ---------
// 128x128 tile, BK=16, 256 threads, 8x8 microtile, double-buffered smem.
#define TM 128
#define TN 128
#define TK 16
__global__ __launch_bounds__(256) void sgemm(const float* __restrict__ A,
                                             const float* __restrict__ B,
                                             const float* __restrict__ bias,
                                             float* __restrict__ C,
                                             int M, int N, int K)
{
    __shared__ __align__(16) float As[2][TK][TM];
    __shared__ __align__(16) float Bs[2][TK][TN];
    int tid = threadIdx.x;
    int bx = blockIdx.x;   // N tile
    int by = blockIdx.y;   // M tile
    const float* Ab = A + (size_t)by * TM * K;
    const float* Bb = B + (size_t)bx * TN;

    int tx = tid & 15, ty = tid >> 4;
    float acc[8][8];
#pragma unroll
    for (int i = 0; i < 8; i++)
#pragma unroll
        for (int j = 0; j < 8; j++) acc[i][j] = 0.f;

    auto loadA = [&](int kt, int buf) {
#pragma unroll
        for (int i = 0; i < 2; i++) {
            int f = tid + i * 256;          // 512 float4 covering 128x16
            int row = f >> 2;
            int k4 = (f & 3) << 2;
            float4 v = *(const float4*)(Ab + (size_t)row * K + kt + k4);
            As[buf][k4+0][row] = v.x;
            As[buf][k4+1][row] = v.y;
            As[buf][k4+2][row] = v.z;
            As[buf][k4+3][row] = v.w;
        }
    };
    auto loadB = [&](int kt, int buf) {
#pragma unroll
        for (int i = 0; i < 2; i++) {
            int f = tid + i * 256;          // 512 float4 covering 16x128
            int row = f >> 5;
            int n4 = (f & 31) << 2;
            float4 v = *(const float4*)(Bb + (size_t)(kt + row) * N + n4);
            *(float4*)&Bs[buf][row][n4] = v;
        }
    };

    loadA(0, 0); loadB(0, 0);
    __syncthreads();
    int nk = K / TK;
    for (int t = 0; t < nk; t++) {
        int buf = t & 1;
        if (t + 1 < nk) { loadA((t + 1) * TK, buf ^ 1); loadB((t + 1) * TK, buf ^ 1); }
#pragma unroll
        for (int k = 0; k < TK; k++) {
            float a[8], b[8];
#pragma unroll
            for (int i = 0; i < 8; i++) a[i] = As[buf][k][ty*8 + i];
#pragma unroll
            for (int j = 0; j < 8; j++) b[j] = Bs[buf][k][tx*8 + j];
#pragma unroll
            for (int i = 0; i < 8; i++)
#pragma unroll
                for (int j = 0; j < 8; j++) acc[i][j] += a[i] * b[j];
        }
        __syncthreads();
    }

    float bv[8];
#pragma unroll
    for (int j = 0; j < 8; j++) bv[j] = bias ? bias[bx*TN + tx*8 + j] : 0.f;
    float* Cb = C + (size_t)(by*TM + ty*8) * N + bx*TN + tx*8;
#pragma unroll
    for (int i = 0; i < 8; i++) {
#pragma unroll
        for (int j = 0; j < 8; j++) {
            Cb[(size_t)i * N + j] = acc[i][j] + bv[j];
        }
    }
}

// ---------------- LayerNorm over last dim (256), one warp per row -----------
__global__ void ln_kernel(const float* __restrict__ in, const float* __restrict__ scale,
                          const float* __restrict__ bias, float* __restrict__ out, int rows)
{
    int warp = (blockIdx.x * blockDim.x + threadIdx.x) >> 5;
    int lane = threadIdx.x & 31;
    if (warp >= rows) return;
    const float* x = in + (size_t)warp * 256;
    float v[8];
    float s = 0.f;
#pragma unroll
    for (int i = 0; i < 8; i++) { v[i] = x[lane + 32*i]; s += v[i]; }
#pragma unroll
    for (int o = 16; o; o >>= 1) s += __shfl_xor_sync(0xffffffffu, s, o);
    float m = s * (1.f/256.f);
    float q = 0.f;
#pragma unroll
    for (int i = 0; i < 8; i++) { float d = v[i] - m; q += d * d; }
#pragma unroll
    for (int o = 16; o; o >>= 1) q += __shfl_xor_sync(0xffffffffu, q, o);
    float inv = rsqrtf(q * (1.f/256.f) + 1e-5f);
    float* o_ = out + (size_t)warp * 256;
#pragma unroll
    for (int i = 0; i < 8; i++) {
        int h = lane + 32*i;
        o_[h] = (v[i] - m) * inv * scale[h] + bias[h];
    }
}

// ---------------- complex affine scan along N -------------------------------
// CTA: one batch b (blockIdx.y), 32 p-lanes (blockIdx.x), 8 chunks of 256 steps.
__global__ __launch_bounds__(256) void scan_kernel(
    const float* __restrict__ Bu, const float* __restrict__ dt,
    const float* __restrict__ Lre, const float* __restrict__ Lim,
    const float* __restrict__ logdelta,
    const float* __restrict__ ire, const float* __restrict__ iim,
    float* __restrict__ X)
{
    __shared__ float dts[SEQ];
    __shared__ float agg[8][32][4];     // [chunk][lane][{Are,Aim,Xre,Xim}]
    __shared__ float carry[8][32][2];
    int b  = blockIdx.y;
    int pg = blockIdx.x;
    int tid = threadIdx.x;
    int pl = tid & 31, c = tid >> 5;
    int p  = pg * 32 + pl;

    for (int i = tid; i < SEQ; i += 256) dts[i] = dt[b * SEQ + i];
    float nE  = -expf(Lre[p]);
    float lim = Lim[p];
    float del = expf(logdelta[p]);
    __syncthreads();

    int n0 = c * 256;
    size_t rowbase = ((size_t)b * SEQ + n0) * 512 + p;
    const float* bup = Bu + rowbase;

    // phase 1: chunk aggregates with zero initial state
    float Ar = 1.f, Ai = 0.f, Xr = 0.f, Xi = 0.f;
    for (int j = 0; j < 256; j++) {
        float dte = dts[n0 + j] * del;
        float mag = expf(nE * dte);
        float sn, cs; sincosf(lim * dte, &sn, &cs);
        float ar = mag * cs, ai = mag * sn;
        float br = bup[(size_t)j * 512], bi = bup[(size_t)j * 512 + 256];
        float nAr = Ar*ar - Ai*ai, nAi = Ar*ai + Ai*ar;
        float nXr = Xr*ar - Xi*ai + br, nXi = Xr*ai + Xi*ar + bi;
        Ar = nAr; Ai = nAi; Xr = nXr; Xi = nXi;
    }
    agg[c][pl][0] = Ar; agg[c][pl][1] = Ai; agg[c][pl][2] = Xr; agg[c][pl][3] = Xi;
    __syncthreads();

    // serial carry across 8 chunks, initial state x0 (handles the x0 injection)
    if (c == 0) {
        float cr = ire[p], ci = iim[p];
        carry[0][pl][0] = cr; carry[0][pl][1] = ci;
        for (int cc = 1; cc < 8; cc++) {
            float Aor = agg[cc-1][pl][0], Aoi = agg[cc-1][pl][1];
            float Xor_ = agg[cc-1][pl][2], Xoi = agg[cc-1][pl][3];
            float nr = Aor*cr - Aoi*ci + Xor_;
            float ni = Aor*ci + Aoi*cr + Xoi;
            cr = nr; ci = ni;
            carry[cc][pl][0] = cr; carry[cc][pl][1] = ci;
        }
    }
    __syncthreads();

    // phase 2: replay with true carry; emit x_left = a*x_prev and x_right = x_left + Bu
    float xr = carry[c][pl][0], xi = carry[c][pl][1];
    const size_t LHALF = (size_t)BNTOT * 512;
    float* xrp = X + rowbase;
    float* xlp = X + LHALF + rowbase;
    for (int j = 0; j < 256; j++) {
        float dte = dts[n0 + j] * del;
        float mag = expf(nE * dte);
        float sn, cs; sincosf(lim * dte, &sn, &cs);
        float ar = mag * cs, ai = mag * sn;
        float br = bup[(size_t)j * 512], bi = bup[(size_t)j * 512 + 256];
        float lr = ar*xr - ai*xi, li2 = ar*xi + ai*xr;   // left limit
        float rr = lr + br,       ri  = li2 + bi;        // right limit
        xlp[(size_t)j * 512]       = lr;
        xlp[(size_t)j * 512 + 256] = li2;
        xrp[(size_t)j * 512]       = rr;
        xrp[(size_t)j * 512 + 256] = ri;
        xr = rr; xi = ri;
    }
}

// ---------------- elementwise kernels ---------------------------------------
__global__ void dup_kernel(const float* __restrict__ a, float* __restrict__ U, int n)
{
    int i = blockIdx.x * blockDim.x + threadIdx.x;
    if (i < n) { float v = a[i]; U[i] = v; U[(size_t)n + i] = v; }
}

__global__ void gelu_kernel(float* __restrict__ x, int n)
{
    int i = blockIdx.x * blockDim.x + threadIdx.x;
    if (i < n) {
        float v = x[i];
        float t = tanhf(0.79788456080286535588f * (v + 0.044715f * v * v * v));
        x[i] = 0.5f * v * (1.f + t);
    }
}

__global__ void glu_acc_kernel(const float* __restrict__ T, float* __restrict__ U, int n)
{
    int i = blockIdx.x * blockDim.x + threadIdx.x;
    if (i < n) {
        int row = i >> 8, h = i & 255;
        float t1 = T[(size_t)row * 512 + h];
        float t2 = T[(size_t)row * 512 + 256 + h];
        U[i] += t1 * (1.f / (1.f + expf(-t2)));
    }
}

__global__ void out_kernel(const float* __restrict__ Uleft, float* __restrict__ out, int n)
{
    int i = blockIdx.x * blockDim.x + threadIdx.x;
    if (i < n) {
        int row = i >> 8;
        int nn = row & (SEQ - 1);
        out[i] = (nn == 0) ? 0.f : Uleft[i];
    }
}

// ---------------- driver -----------------------------------------------------
extern "C" void kernel_launch(void* const* d_in, const int* in_sizes, int n_in,
                              void* d_out, int out_size)
{
    (void)in_sizes; (void)n_in; (void)out_size;
    const float* x_payload = (const float*)d_in[0];
    const float* dt        = (const float*)d_in[1];
    const float* embed_W   = (const float*)d_in[2];
    const float* embed_b   = (const float*)d_in[3];
    const float* ln_scale  = (const float*)d_in[4];
    const float* ln_bias   = (const float*)d_in[5];
    const float* Lambda_re = (const float*)d_in[6];
    const float* Lambda_im = (const float*)d_in[7];
    const float* log_delta = (const float*)d_in[8];
    const float* B_re      = (const float*)d_in[9];
    const float* B_im      = (const float*)d_in[10];
    const float* C_re      = (const float*)d_in[11];
    const float* C_im      = (const float*)d_in[12];
    const float* W1        = (const float*)d_in[13];
    const float* b1        = (const float*)d_in[14];
    const float* W2        = (const float*)d_in[15];
    const float* b2        = (const float*)d_in[16];
    const float* init_re   = (const float*)d_in[17];
    const float* init_im   = (const float*)d_in[18];
    float* out = (float*)d_out;

    float *V, *Bu, *X, *Y, *T, *U, *W;
    cudaGetSymbolAddress((void**)&V,  g_V);
    cudaGetSymbolAddress((void**)&Bu, g_Bu);
    cudaGetSymbolAddress((void**)&X,  g_X);
    cudaGetSymbolAddress((void**)&Y,  g_Y);
    cudaGetSymbolAddress((void**)&T,  g_T);
    cudaGetSymbolAddress((void**)&U,  g_U);
    cudaGetSymbolAddress((void**)&W,  g_W);

    // pack fused weights
    {
        int total = NLAYER * LS;
        pack_kernel<<<(total + 255) / 256, 256>>>(B_re, B_im, C_re, C_im, W1, W2, b1, b2, W);
    }

    // alpha = x_payload @ embed_W + embed_b  -> duplicate into right_u / left_u
    sgemm<<<dim3(2, 256), 256>>>(x_payload, embed_W, embed_b, Y, BNTOT, 256, 256);
    dup_kernel<<<(BNTOT * 256 + 255) / 256, 256>>>(Y, U, BNTOT * 256);

    const int n1 = BNTOT * 256;          // 8.39M  (one stream)
    const int n2 = 2 * BNTOT * 256;      // 16.8M  (both streams)

    for (int l = 0; l < NLAYER; l++) {
        float* Wl = W + (size_t)l * LS;
        // v = LN(right_u)
        ln_kernel<<<4096, 256>>>(U, ln_scale + l * 256, ln_bias + l * 256, V, BNTOT);
        // Bu = v @ [B_re | B_im]
        sgemm<<<dim3(4, 256), 256>>>(V, Wl, nullptr, Bu, BNTOT, 512, 256);
        // scan -> X = [x_right | x_left] x [re|im]
        scan_kernel<<<dim3(8, 16), 256>>>(Bu, dt,
                                          Lambda_re + l * 256, Lambda_im + l * 256,
                                          log_delta + l * 256,
                                          init_re + l * 256, init_im + l * 256, X);
        // Y = X @ [C_re ; -C_im]  (both streams stacked on M)
        sgemm<<<dim3(2, 512), 256>>>(X, Wl + 131072, nullptr, Y, 2 * BNTOT, 256, 512);
        // g = gelu(Y) in place
        gelu_kernel<<<(n2 + 255) / 256, 256>>>(Y, n2);
        // T = g @ [W1 | W2] + [b1 | b2]
        sgemm<<<dim3(4, 512), 256>>>(Y, Wl + 262144, Wl + 393216, T, 2 * BNTOT, 512, 256);
        // U += T1 * sigmoid(T2)
        glu_acc_kernel<<<(n2 + 255) / 256, 256>>>(T, U, n2);
    }

    // out = [zeros ; left_u[:,1:]]
    out_kernel<<<(n1 + 255) / 256, 256>>>(U + (size_t)BNTOT * 256, out, n1);
}

// round 5
// speedup vs baseline: 1.1991x; 1.1991x over previous
#include <cuda_runtime.h>
#include <cuda_bf16.h>
#include <cstdint>
#include <math.h>

// Problem constants
#define BATCH 16
#define SEQ   2048
#define NLAYER 4
#define BNTOT (BATCH*SEQ)          // 32768
#define LSP   393728               // packed per-layer weight stride (floats)

// ---------------- scratch (device globals) ----------------------------------
__device__ float g_V [(size_t)BNTOT*256];        // LN output
__device__ float g_Bu[(size_t)BNTOT*512];        // [Bu_re | Bu_im]
__device__ float g_X [(size_t)2*BNTOT*512];      // x_right rows 0..BN-1, x_left rows BN..
__device__ float g_Y [(size_t)2*BNTOT*256];      // gelu(y)
__device__ float g_U [(size_t)2*BNTOT*256];      // right_u rows 0..BN-1, left_u rows BN..
__device__ float g_W [(size_t)NLAYER*LSP + 65536]; // packed transposed weights + embed

// ---------------- helpers ----------------------------------------------------
static __device__ __forceinline__ uint32_t smem_u32(const void* p) {
    uint32_t a;
    asm("{ .reg .u64 t; cvta.to.shared.u64 t, %1; cvt.u32.u64 %0, t; }" : "=r"(a) : "l"(p));
    return a;
}
static __device__ __forceinline__ void cp16(uint32_t dst, const void* src) {
    asm volatile("cp.async.cg.shared.global [%0], [%1], 16;" :: "r"(dst), "l"(src));
}
#define CP_COMMIT() asm volatile("cp.async.commit_group;" ::: "memory")
#define CP_WAIT1()  asm volatile("cp.async.wait_group 1;" ::: "memory")
#define CP_WAIT0()  asm volatile("cp.async.wait_group 0;" ::: "memory")

static __device__ __forceinline__ uint32_t to_tf32(float x) {
    uint32_t r;
    asm("cvt.rna.tf32.f32 %0, %1;" : "=r"(r) : "f"(x));
    return r;
}
// split x into tf32 hi + tf32 lo (3xTF32 decomposition)
static __device__ __forceinline__ void split_tf32(float x, uint32_t& hi, uint32_t& lo) {
    hi = to_tf32(x);
    float res = x - __uint_as_float(hi);
    lo = to_tf32(res);
}
static __device__ __forceinline__ void mma8(float* c, const uint32_t* a, const uint32_t* b) {
    asm volatile("mma.sync.aligned.m16n8k8.row.col.f32.tf32.tf32.f32 "
                 "{%0,%1,%2,%3}, {%4,%5,%6,%7}, {%8,%9}, {%0,%1,%2,%3};"
                 : "+f"(c[0]), "+f"(c[1]), "+f"(c[2]), "+f"(c[3])
                 : "r"(a[0]), "r"(a[1]), "r"(a[2]), "r"(a[3]), "r"(b[0]), "r"(b[1]));
}

// ---------------- 3xTF32 mma.sync GEMM ---------------------------------------
// C(128x128 per CTA) = A(M x K, K-major) @ Bt(N x K, K-major)^T
// 8 warps (2m x 4n), warp tile 64x32, BK=32, 3-stage cp.async pipeline.
// Epilogue modes:
//  0: +bias, dual store to C and C2 (embed -> right_u/left_u)
//  1: plain store with row stride Ntot (Bu)
//  2: gelu store (g), stride 256
//  3: interleaved GLU: pairs (t1,t2); C[m][gc/2] += (t1+b1)*sigmoid(t2+b2)
#define BKK   32
#define PADF  36                         // floats per smem row (144B)
#define ASTG  (128*PADF)                 // floats per operand per stage
#define STGF  (2*ASTG)
#define NSTG  3
#define GSMEM (NSTG*STGF*4)              // 110592 bytes

static __device__ __forceinline__ void load_stage(uint32_t sb, int s,
                                                  const float* Ab, const float* Bb,
                                                  int K, int kt, int tid) {
    uint32_t st = sb + (uint32_t)s * (STGF * 4);
#pragma unroll
    for (int i = 0; i < 4; i++) {            // A: 128 rows x 32 floats
        int f = tid + i * 256;
        int row = f >> 3, ch = f & 7;
        cp16(st + row * 144 + ch * 16, Ab + (size_t)row * K + kt + ch * 4);
    }
#pragma unroll
    for (int i = 0; i < 4; i++) {            // B: 128 rows x 32 floats
        int f = tid + i * 256;
        int row = f >> 3, ch = f & 7;
        cp16(st + ASTG * 4 + row * 144 + ch * 16, Bb + (size_t)row * K + kt + ch * 4);
    }
}

__global__ __launch_bounds__(256, 1) void gemm_mma(
    const float* __restrict__ A, const float* __restrict__ Bt,
    const float* __restrict__ bias, float* __restrict__ C, float* __restrict__ C2,
    int Ntot, int K, int mode)
{
    extern __shared__ float sm[];
    uint32_t sb = smem_u32(sm);
    int tid = threadIdx.x;
    int warp = tid >> 5, lane = tid & 31;
    int wm = warp & 1, wn = warp >> 1;
    int bx = blockIdx.x, by = blockIdx.y;

    const float* Ab = A + (size_t)by * 128 * K;
    const float* Bb = Bt + (size_t)bx * 128 * K;
    int NT = K / BKK;

    float acc[4][4][4];
#pragma unroll
    for (int mt = 0; mt < 4; mt++)
#pragma unroll
        for (int nt = 0; nt < 4; nt++)
#pragma unroll
            for (int e = 0; e < 4; e++) acc[mt][nt][e] = 0.f;

    load_stage(sb, 0, Ab, Bb, K, 0, tid); CP_COMMIT();
    load_stage(sb, 1, Ab, Bb, K, BKK, tid); CP_COMMIT();

    int r0 = wm * 64 + (lane >> 2);          // A row base within tile
    int n0 = wn * 32 + (lane >> 2);          // B row base within tile
    int kb = lane & 3;

    for (int t = 0; t < NT; t++) {
        if (t + 1 < NT) CP_WAIT1(); else CP_WAIT0();
        __syncthreads();
        const float* Ss = sm + (t % 3) * STGF;
        const float* SsB = Ss + ASTG;
#pragma unroll
        for (int kk = 0; kk < 4; kk++) {
            int k0 = kk * 8 + kb;
            uint32_t ah[4][4], al[4][4], bh[4][2], bl[4][2];
#pragma unroll
            for (int mt = 0; mt < 4; mt++) {
                int rr = r0 + mt * 16;
                split_tf32(Ss[rr * PADF + k0],           ah[mt][0], al[mt][0]);
                split_tf32(Ss[(rr + 8) * PADF + k0],     ah[mt][1], al[mt][1]);
                split_tf32(Ss[rr * PADF + k0 + 4],       ah[mt][2], al[mt][2]);
                split_tf32(Ss[(rr + 8) * PADF + k0 + 4], ah[mt][3], al[mt][3]);
            }
#pragma unroll
            for (int nt = 0; nt < 4; nt++) {
                int nr = n0 + nt * 8;
                split_tf32(SsB[nr * PADF + k0],     bh[nt][0], bl[nt][0]);
                split_tf32(SsB[nr * PADF + k0 + 4], bh[nt][1], bl[nt][1]);
            }
            // 3xTF32: small cross terms first, dominant term last
#pragma unroll
            for (int mt = 0; mt < 4; mt++)
#pragma unroll
                for (int nt = 0; nt < 4; nt++) {
                    mma8(acc[mt][nt], ah[mt], bl[nt]);
                    mma8(acc[mt][nt], al[mt], bh[nt]);
                    mma8(acc[mt][nt], ah[mt], bh[nt]);
                }
        }
        __syncthreads();
        if (t + 2 < NT) { load_stage(sb, (t + 2) % 3, Ab, Bb, K, (t + 2) * BKK, tid); CP_COMMIT(); }
    }

    // ---------------- epilogue ----------------
    int rowb = by * 128 + wm * 64 + (lane >> 2);
    int colb = bx * 128 + wn * 32 + 2 * (lane & 3);
#pragma unroll
    for (int mt = 0; mt < 4; mt++) {
#pragma unroll
        for (int half = 0; half < 2; half++) {
            size_t r = (size_t)(rowb + mt * 16 + half * 8);
#pragma unroll
            for (int nt = 0; nt < 4; nt++) {
                float v0 = acc[mt][nt][half * 2 + 0];
                float v1 = acc[mt][nt][half * 2 + 1];
                int gc = colb + nt * 8;
                if (mode == 0) {
                    v0 += bias[gc]; v1 += bias[gc + 1];
                    float2 v = make_float2(v0, v1);
                    *(float2*)(C  + r * 256 + gc) = v;
                    *(float2*)(C2 + r * 256 + gc) = v;
                } else if (mode == 1) {
                    *(float2*)(C + r * (size_t)Ntot + gc) = make_float2(v0, v1);
                } else if (mode == 2) {
                    float t0 = tanhf(0.79788456080286535588f * (v0 + 0.044715f * v0 * v0 * v0));
                    float t1 = tanhf(0.79788456080286535588f * (v1 + 0.044715f * v1 * v1 * v1));
                    *(float2*)(C + r * 256 + gc) =
                        make_float2(0.5f * v0 * (1.f + t0), 0.5f * v1 * (1.f + t1));
                } else {
                    float t1 = v0 + bias[gc];
                    float t2 = v1 + bias[gc + 1];
                    C[r * 256 + (gc >> 1)] += t1 * (1.f / (1.f + expf(-t2)));
                }
            }
        }
    }
}

// ---------------- weight packing (transposed, K-major rows) ------------------
__global__ void pack_kernel(const float* __restrict__ B_re, const float* __restrict__ B_im,
                            const float* __restrict__ C_re, const float* __restrict__ C_im,
                            const float* __restrict__ W1,   const float* __restrict__ W2,
                            const float* __restrict__ b1,   const float* __restrict__ b2,
                            const float* __restrict__ embW, float* __restrict__ W)
{
    int idx = blockIdx.x * blockDim.x + threadIdx.x;
    int total = NLAYER * LSP + 65536;
    if (idx >= total) return;
    float val;
    if (idx >= NLAYER * LSP) {               // embed^T: Et[n][k] = embW[k][n]
        int r = idx - NLAYER * LSP;
        int n = r >> 8, k = r & 255;
        val = embW[k * 256 + n];
    } else {
        int l = idx / LSP;
        int r = idx - l * LSP;
        if (r < 131072) {                    // Bt[j][h] = B_re/B_im[h][j]
            int j = r >> 8, h = r & 255;
            val = (j < 256) ? B_re[l * 65536 + h * 256 + j]
                            : B_im[l * 65536 + h * 256 + (j - 256)];
        } else if (r < 262144) {             // Ct[h][k] = C_re[k][h] / -C_im
            int r2 = r - 131072;
            int h = r2 >> 9, k = r2 & 511;
            val = (k < 256) ? C_re[l * 65536 + k * 256 + h]
                            : -C_im[l * 65536 + (k - 256) * 256 + h];
        } else if (r < 393216) {             // Wt[n][k], n even->W1 col n/2, odd->W2
            int r3 = r - 262144;
            int n = r3 >> 8, k = r3 & 255;
            val = (n & 1) ? W2[l * 65536 + k * 256 + (n >> 1)]
                          : W1[l * 65536 + k * 256 + (n >> 1)];
        } else {                             // interleaved bias
            int n = r - 393216;
            val = (n & 1) ? b2[l * 256 + (n >> 1)] : b1[l * 256 + (n >> 1)];
        }
    }
    W[idx] = val;
}

// ---------------- LayerNorm (one warp per row of 256) ------------------------
__global__ void ln_kernel(const float* __restrict__ in, const float* __restrict__ scale,
                          const float* __restrict__ bias, float* __restrict__ out, int rows)
{
    int warp = (blockIdx.x * blockDim.x + threadIdx.x) >> 5;
    int lane = threadIdx.x & 31;
    if (warp >= rows) return;
    const float* x = in + (size_t)warp * 256;
    float v[8], s = 0.f;
#pragma unroll
    for (int i = 0; i < 8; i++) { v[i] = x[lane + 32 * i]; s += v[i]; }
#pragma unroll
    for (int o = 16; o; o >>= 1) s += __shfl_xor_sync(0xffffffffu, s, o);
    float mn = s * (1.f / 256.f), q = 0.f;
#pragma unroll
    for (int i = 0; i < 8; i++) { float d = v[i] - mn; q += d * d; }
#pragma unroll
    for (int o = 16; o; o >>= 1) q += __shfl_xor_sync(0xffffffffu, q, o);
    float inv = rsqrtf(q * (1.f / 256.f) + 1e-5f);
    float* o_ = out + (size_t)warp * 256;
#pragma unroll
    for (int i = 0; i < 8; i++) {
        int h = lane + 32 * i;
        o_[h] = (v[i] - mn) * inv * scale[h] + bias[h];
    }
}

// ---------------- complex affine scan along N --------------------------------
__global__ __launch_bounds__(256) void scan_kernel(
    const float* __restrict__ Bu, const float* __restrict__ dt,
    const float* __restrict__ Lre, const float* __restrict__ Lim,
    const float* __restrict__ logdelta,
    const float* __restrict__ ire, const float* __restrict__ iim,
    float* __restrict__ X)
{
    __shared__ float dts[SEQ];
    __shared__ float agg[8][32][4];
    __shared__ float carry[8][32][2];
    int b = blockIdx.y, pg = blockIdx.x;
    int tid = threadIdx.x;
    int pl = tid & 31, c = tid >> 5;
    int p = pg * 32 + pl;

    for (int i = tid; i < SEQ; i += 256) dts[i] = dt[b * SEQ + i];
    float nE = -expf(Lre[p]);
    float lim = Lim[p];
    float del = expf(logdelta[p]);
    __syncthreads();

    int n0 = c * 256;
    size_t rowbase = ((size_t)b * SEQ + n0) * 512 + p;
    const float* bup = Bu + rowbase;

    float Ar = 1.f, Ai = 0.f, Xr = 0.f, Xi = 0.f;
    for (int j = 0; j < 256; j++) {
        float dte = dts[n0 + j] * del;
        float mag = expf(nE * dte);
        float sn, cs; sincosf(lim * dte, &sn, &cs);
        float ar = mag * cs, ai = mag * sn;
        float br = bup[(size_t)j * 512], bi = bup[(size_t)j * 512 + 256];
        float nAr = Ar * ar - Ai * ai, nAi = Ar * ai + Ai * ar;
        float nXr = Xr * ar - Xi * ai + br, nXi = Xr * ai + Xi * ar + bi;
        Ar = nAr; Ai = nAi; Xr = nXr; Xi = nXi;
    }
    agg[c][pl][0] = Ar; agg[c][pl][1] = Ai; agg[c][pl][2] = Xr; agg[c][pl][3] = Xi;
    __syncthreads();

    if (c == 0) {
        float cr = ire[p], ci = iim[p];
        carry[0][pl][0] = cr; carry[0][pl][1] = ci;
        for (int cc = 1; cc < 8; cc++) {
            float Aor = agg[cc-1][pl][0], Aoi = agg[cc-1][pl][1];
            float Xor_ = agg[cc-1][pl][2], Xoi = agg[cc-1][pl][3];
            float nr = Aor * cr - Aoi * ci + Xor_;
            float ni = Aor * ci + Aoi * cr + Xoi;
            cr = nr; ci = ni;
            carry[cc][pl][0] = cr; carry[cc][pl][1] = ci;
        }
    }
    __syncthreads();

    float xr = carry[c][pl][0], xi = carry[c][pl][1];
    const size_t LHALF = (size_t)BNTOT * 512;
    float* xrp = X + rowbase;
    float* xlp = X + LHALF + rowbase;
    for (int j = 0; j < 256; j++) {
        float dte = dts[n0 + j] * del;
        float mag = expf(nE * dte);
        float sn, cs; sincosf(lim * dte, &sn, &cs);
        float ar = mag * cs, ai = mag * sn;
        float br = bup[(size_t)j * 512], bi = bup[(size_t)j * 512 + 256];
        float lr = ar * xr - ai * xi, li2 = ar * xi + ai * xr;
        float rr = lr + br,           ri  = li2 + bi;
        xlp[(size_t)j * 512]       = lr;
        xlp[(size_t)j * 512 + 256] = li2;
        xrp[(size_t)j * 512]       = rr;
        xrp[(size_t)j * 512 + 256] = ri;
        xr = rr; xi = ri;
    }
}

__global__ void out_kernel(const float* __restrict__ Uleft, float* __restrict__ out, int n)
{
    int i = blockIdx.x * blockDim.x + threadIdx.x;
    if (i < n) {
        int row = i >> 8;
        int nn = row & (SEQ - 1);
        out[i] = (nn == 0) ? 0.f : Uleft[i];
    }
}

// ---------------- driver -----------------------------------------------------
extern "C" void kernel_launch(void* const* d_in, const int* in_sizes, int n_in,
                              void* d_out, int out_size)
{
    (void)in_sizes; (void)n_in; (void)out_size;
    const float* x_payload = (const float*)d_in[0];
    const float* dt        = (const float*)d_in[1];
    const float* embed_W   = (const float*)d_in[2];
    const float* embed_b   = (const float*)d_in[3];
    const float* ln_scale  = (const float*)d_in[4];
    const float* ln_bias   = (const float*)d_in[5];
    const float* Lambda_re = (const float*)d_in[6];
    const float* Lambda_im = (const float*)d_in[7];
    const float* log_delta = (const float*)d_in[8];
    const float* B_re      = (const float*)d_in[9];
    const float* B_im      = (const float*)d_in[10];
    const float* C_re      = (const float*)d_in[11];
    const float* C_im      = (const float*)d_in[12];
    const float* W1        = (const float*)d_in[13];
    const float* b1        = (const float*)d_in[14];
    const float* W2        = (const float*)d_in[15];
    const float* b2        = (const float*)d_in[16];
    const float* init_re   = (const float*)d_in[17];
    const float* init_im   = (const float*)d_in[18];
    float* out = (float*)d_out;

    float *V, *Bu, *X, *Y, *U, *W;
    cudaGetSymbolAddress((void**)&V,  g_V);
    cudaGetSymbolAddress((void**)&Bu, g_Bu);
    cudaGetSymbolAddress((void**)&X,  g_X);
    cudaGetSymbolAddress((void**)&Y,  g_Y);
    cudaGetSymbolAddress((void**)&U,  g_U);
    cudaGetSymbolAddress((void**)&W,  g_W);

    cudaFuncSetAttribute(gemm_mma, cudaFuncAttributeMaxDynamicSharedMemorySize, GSMEM);

    {
        int total = NLAYER * LSP + 65536;
        pack_kernel<<<(total + 255) / 256, 256>>>(B_re, B_im, C_re, C_im, W1, W2,
                                                  b1, b2, embed_W, W);
    }

    const int n1 = BNTOT * 256;
    float* Emb = W + (size_t)NLAYER * LSP;
    float* U1  = U + (size_t)BNTOT * 256;

    // alpha = x @ embed_W + b -> right_u and left_u   (mode 0)
    gemm_mma<<<dim3(2, 256), 256, GSMEM>>>(x_payload, Emb, embed_b, U, U1, 256, 256, 0);

    for (int l = 0; l < NLAYER; l++) {
        float* Wl = W + (size_t)l * LSP;
        ln_kernel<<<4096, 256>>>(U, ln_scale + l * 256, ln_bias + l * 256, V, BNTOT);
        // Bu = v @ [B_re|B_im]   (mode 1, out stride 512)
        gemm_mma<<<dim3(4, 256), 256, GSMEM>>>(V, Wl, nullptr, Bu, nullptr, 512, 256, 1);
        scan_kernel<<<dim3(8, 16), 256>>>(Bu, dt,
                                          Lambda_re + l * 256, Lambda_im + l * 256,
                                          log_delta + l * 256,
                                          init_re + l * 256, init_im + l * 256, X);
        // g = gelu(X @ [C_re;-C_im])   (mode 2, both streams stacked on M)
        gemm_mma<<<dim3(2, 512), 256, GSMEM>>>(X, Wl + 131072, nullptr, Y, nullptr, 256, 512, 2);
        // U += (g@W1+b1)*sigmoid(g@W2+b2)  (mode 3, interleaved columns)
        gemm_mma<<<dim3(4, 512), 256, GSMEM>>>(Y, Wl + 262144, Wl + 393216, U, nullptr, 256, 256, 3);
    }

    out_kernel<<<(n1 + 255) / 256, 256>>>(U1, out, n1);
}